// round 10
// baseline (speedup 1.0000x reference)
#include <cuda_runtime.h>
#include <cuda_bf16.h>
#include <math.h>

// Problem constants
#define BATCH 256
#define DDIM  511
#define HDIM  5120
#define QPARTS 4        // CTAs per batch for the quadratic form
#define SPLITK 8        // K-splits for GEMM2
#define LDC2   512      // padded leading dim for GEMM2 partials

// Scratch (device globals; no allocation allowed)
__device__ float g_h[BATCH * HDIM];                      // hidden [256,5120]
__device__ float g_phi[BATCH * DDIM];                    // phi [256,511]
__device__ float g_phi_part[SPLITK * BATCH * LDC2];      // split-K partials
__device__ float g_quadp[BATCH * QPARTS];                // partial quad forms

// ---------------------------------------------------------------------------
// Packed fp32x2 helpers (Blackwell f32x2 SIMD on the FMA pipe).
// fma.rn.f32x2 rounds identically to scalar fmaf -> bit-exact fp32 numerics.
// ---------------------------------------------------------------------------
__device__ __forceinline__ void fma2(unsigned long long& d,
                                     unsigned long long a,
                                     unsigned long long b) {
    asm("fma.rn.f32x2 %0, %1, %2, %0;" : "+l"(d) : "l"(a), "l"(b));
}
__device__ __forceinline__ float2 unpack2(unsigned long long v) {
    float lo, hi;
    asm("mov.b64 {%0, %1}, %2;" : "=f"(lo), "=f"(hi) : "l"(v));
    return make_float2(lo, hi);
}

// ---------------------------------------------------------------------------
// f32x2 tiled GEMM: C[M,N] = act(A[M,K] * B[N,K]^T (+ bias))
// Conflict-engineered smem (2-way worst-case STS, conflict-free LDS.128) +
// REGISTER DOUBLE BUFFERING: operands for kk+1 are loaded before the 16
// FMA2s of kk issue, stretching LDS->use distance past the 29-cyc latency
// so 2 warps/SMSP suffice to keep the FMA pipe fed.
// PARTIAL: split-K over gridDim.z, store raw partials with leading dim ldc.
// ---------------------------------------------------------------------------
template<int BM, int BN, int BK, bool RELU, bool PARTIAL>
__global__ __launch_bounds__((BM/4)*(BN/8))
void gemm2x_kernel(const float* __restrict__ A,
                   const float* __restrict__ B,
                   const float* __restrict__ bias,
                   float* __restrict__ C,
                   int M, int N, int K, int kPerSplit, int ldc)
{
    constexpr int TM = 4, TN = 8;
    constexpr int NX = BN / TN;           // threads along N
    constexpr int NT = (BM/TM) * NX;
    constexpr int BMP = BM + 2;           // padded As2 row (float2 units)
    constexpr int BNP = BN + 4;           // padded Bs row (float units)

    __shared__ __align__(16) float2 As2[BK][BMP];  // duplicated pairs {a,a}
    __shared__ __align__(16) float  Bs[BK][BNP];

    const int tid = threadIdx.x;
    const int tx  = tid % NX;
    const int ty  = tid / NX;

    const int m0 = blockIdx.y * BM;
    const int n0 = blockIdx.x * BN;

    const int kbeg = blockIdx.z * kPerSplit;
    const int kend = min(kbeg + kPerSplit, K);

    unsigned long long acc[TM][4];
    #pragma unroll
    for (int i = 0; i < TM; i++)
        #pragma unroll
        for (int j = 0; j < 4; j++)
            acc[i][j] = 0ull;

    for (int k0 = kbeg; k0 < kend; k0 += BK) {
        // As2[kk][i] = {A[m0+i][k0+kk], same}; kk fast in tid (coalesced LDG)
        #pragma unroll
        for (int idx = tid; idx < BM * BK; idx += NT) {
            int kk = idx % BK, i = idx / BK;
            int m = m0 + i, k = k0 + kk;
            float v = 0.0f;
            if (m < M && k < kend) v = A[(size_t)m * K + k];
            As2[kk][i] = make_float2(v, v);
        }
        // Bs[kk][j] = B[n0+j][k0+kk]; kk fast in tid (coalesced LDG)
        #pragma unroll
        for (int idx = tid; idx < BN * BK; idx += NT) {
            int kk = idx % BK, j = idx / BK;
            int n = n0 + j, k = k0 + kk;
            float v = 0.0f;
            if (n < N && k < kend) v = B[(size_t)n * K + k];
            Bs[kk][j] = v;
        }
        __syncthreads();

        // Register double-buffered mainloop
        ulonglong2 a01 = *(const ulonglong2*)(&As2[0][ty * TM]);
        ulonglong2 a23 = *(const ulonglong2*)(&As2[0][ty * TM + 2]);
        ulonglong2 blo = *(const ulonglong2*)(&Bs[0][tx * 4]);
        ulonglong2 bhi = *(const ulonglong2*)(&Bs[0][BN/2 + tx * 4]);

        #pragma unroll
        for (int kk = 0; kk < BK; kk++) {
            const unsigned long long ra[TM] = { a01.x, a01.y, a23.x, a23.y };
            const unsigned long long rb[4]  = { blo.x, blo.y, bhi.x, bhi.y };

            if (kk + 1 < BK) {            // prefetch next kk before FMAs
                a01 = *(const ulonglong2*)(&As2[kk + 1][ty * TM]);
                a23 = *(const ulonglong2*)(&As2[kk + 1][ty * TM + 2]);
                blo = *(const ulonglong2*)(&Bs[kk + 1][tx * 4]);
                bhi = *(const ulonglong2*)(&Bs[kk + 1][BN/2 + tx * 4]);
            }

            #pragma unroll
            for (int i = 0; i < TM; i++)
                #pragma unroll
                for (int j = 0; j < 4; j++)
                    fma2(acc[i][j], ra[i], rb[j]);
        }
        __syncthreads();
    }

    // Store: cols for pair j: j<2 -> n0 + tx*4 + 2j(+1); j>=2 -> +BN/2
    #pragma unroll
    for (int i = 0; i < TM; i++) {
        const int m = m0 + ty * TM + i;
        if (m >= M) continue;
        #pragma unroll
        for (int j = 0; j < 4; j++) {
            const int base = (j < 2) ? (n0 + tx * 4 + 2 * j)
                                     : (n0 + BN/2 + tx * 4 + 2 * (j - 2));
            const float2 v = unpack2(acc[i][j]);
            if (PARTIAL) {
                float* __restrict__ Cz = C + (size_t)blockIdx.z * M * ldc;
                if (base     < N) Cz[(size_t)m * ldc + base]     = v.x;
                if (base + 1 < N) Cz[(size_t)m * ldc + base + 1] = v.y;
            } else {
                if (base < N) {
                    float a = v.x + bias[base];
                    if (RELU) a = fmaxf(a, 0.0f);
                    C[(size_t)m * ldc + base] = a;
                }
                if (base + 1 < N) {
                    float a = v.y + bias[base + 1];
                    if (RELU) a = fmaxf(a, 0.0f);
                    C[(size_t)m * ldc + base + 1] = a;
                }
            }
        }
    }
}

// ---------------------------------------------------------------------------
// Split-K reduce: phi[m][n] = sum_z part[z][m][n] + bias[n]
// ---------------------------------------------------------------------------
__global__ __launch_bounds__(256)
void reduce_phi_kernel(const float* __restrict__ bias)
{
    const int idx = blockIdx.x * 256 + threadIdx.x;
    if (idx >= BATCH * DDIM) return;
    const int m = idx / DDIM;
    const int n = idx % DDIM;
    float s = bias[n];
    #pragma unroll
    for (int z = 0; z < SPLITK; z++)
        s += g_phi_part[(size_t)z * BATCH * LDC2 + (size_t)m * LDC2 + n];
    g_phi[idx] = s;
}

// ---------------------------------------------------------------------------
// Batched quadratic form, SYMMETRIC lower-triangle only (134MB traffic).
//   quad = 2*sum_{j<i} M_ij p_i p_j + sum_i M_ii p_i^2
// TWO ROWS PER WARP per outer iteration (i and i+32) with independent
// accumulators -> 2x the outstanding LDG.128s per thread (the R9 profile
// showed 44% DRAM at 31% issue with regs=32: MLP-starved, not BW-bound).
// ---------------------------------------------------------------------------
__global__ __launch_bounds__(256)
void quad_kernel(const float* __restrict__ Minv)
{
    const int b    = blockIdx.x / QPARTS;
    const int part = blockIdx.x % QPARTS;
    const float* __restrict__ Mb = Minv + (size_t)b * DDIM * DDIM;
    const float* __restrict__ pb = g_phi + (size_t)b * DDIM;

    __shared__ float ph[DDIM];
    const int tid = threadIdx.x;
    for (int i = tid; i < DDIM; i += 256) ph[i] = pb[i];
    __syncthreads();

    const int warp = tid >> 5;
    const int lane = tid & 31;
    const int G    = QPARTS * 8;          // 32 warps chip-wide per batch

    float accOff  = 0.0f;
    float accDiag = 0.0f;                 // lane 0 only

    for (int i1 = part * 8 + warp; i1 < DDIM; i1 += 2 * G) {
        const int i2   = i1 + G;
        const bool has2 = (i2 < DDIM);

        const float* __restrict__ r1 = Mb + (size_t)i1 * DDIM;
        const float* __restrict__ r2 = Mb + (size_t)i2 * DDIM;
        const float p1 = ph[i1];
        const float p2 = has2 ? ph[i2] : 0.0f;

        float s1 = 0.0f, s2 = 0.0f;

        int h1 = (4 - (int)(((size_t)r1 >> 2) & 3)) & 3;  if (h1 > i1) h1 = i1;
        int h2 = (4 - (int)(((size_t)r2 >> 2) & 3)) & 3;  if (h2 > i2) h2 = i2;

        if (lane < h1)          s1 = fmaf(__ldcs(r1 + lane), ph[lane], s1);
        if (has2 && lane < h2)  s2 = fmaf(__ldcs(r2 + lane), ph[lane], s2);

        const int nv1 = (i1 - h1) >> 2;
        const int nv2 = has2 ? ((i2 - h2) >> 2) : 0;
        const int nvm = nv1 > nv2 ? nv1 : nv2;
        const float4* __restrict__ v1 = (const float4*)(r1 + h1);
        const float4* __restrict__ v2 = (const float4*)(r2 + h2);

        #pragma unroll 2
        for (int v = lane; v < nvm; v += 32) {
            if (v < nv1) {                       // row 1 stream
                const float4 m = __ldcs(v1 + v);
                const int j = h1 + 4 * v;
                s1 = fmaf(m.x, ph[j    ], s1);
                s1 = fmaf(m.y, ph[j + 1], s1);
                s1 = fmaf(m.z, ph[j + 2], s1);
                s1 = fmaf(m.w, ph[j + 3], s1);
            }
            if (v < nv2) {                       // row 2 stream (independent)
                const float4 m = __ldcs(v2 + v);
                const int j = h2 + 4 * v;
                s2 = fmaf(m.x, ph[j    ], s2);
                s2 = fmaf(m.y, ph[j + 1], s2);
                s2 = fmaf(m.z, ph[j + 2], s2);
                s2 = fmaf(m.w, ph[j + 3], s2);
            }
        }

        const int t1 = h1 + 4 * nv1;
        if (t1 + lane < i1)
            s1 = fmaf(__ldcs(r1 + t1 + lane), ph[t1 + lane], s1);
        if (has2) {
            const int t2 = h2 + 4 * nv2;
            if (t2 + lane < i2)
                s2 = fmaf(__ldcs(r2 + t2 + lane), ph[t2 + lane], s2);
        }

        accOff = fmaf(p1, s1, accOff);
        accOff = fmaf(p2, s2, accOff);
        if (lane == 0) {
            accDiag = fmaf(__ldg(r1 + i1) * p1, p1, accDiag);
            if (has2) accDiag = fmaf(__ldg(r2 + i2) * p2, p2, accDiag);
        }
    }

    float acc = 2.0f * accOff + accDiag;
    #pragma unroll
    for (int o = 16; o; o >>= 1)
        acc += __shfl_xor_sync(0xFFFFFFFFu, acc, o);

    __shared__ float wsum[8];
    if (lane == 0) wsum[warp] = acc;
    __syncthreads();
    if (tid == 0) {
        float s = 0.0f;
        #pragma unroll
        for (int w = 0; w < 8; w++) s += wsum[w];
        g_quadp[b * QPARTS + part] = s;
    }
}

// ---------------------------------------------------------------------------
// Epilogue: combine quad parts; phi_n = phi/sqrt(quad); tiny MLP -> lambda;
// out = sign(phi_n) * max(0, |phi_n| - 0.1*lambda)
// ---------------------------------------------------------------------------
__global__ __launch_bounds__(256)
void epilogue_kernel(const float* __restrict__ st_w1,
                     const float* __restrict__ st_b1,
                     const float* __restrict__ st_w2,
                     const float* __restrict__ st_b2,
                     float* __restrict__ out)
{
    const int idx = blockIdx.x * 256 + threadIdx.x;
    if (idx >= BATCH * DDIM) return;
    const int b = idx / DDIM;

    float q = 0.0f;
    #pragma unroll
    for (int p = 0; p < QPARTS; p++) q += g_quadp[b * QPARTS + p];

    const float inv = rsqrtf(q);
    const float x   = g_phi[idx] * inv;

    float lam = st_b2[0];
    #pragma unroll
    for (int k = 0; k < 5; k++)
        lam = fmaf(fmaxf(fmaf(x, st_w1[k], st_b1[k]), 0.0f), st_w2[k], lam);
    lam = fabsf(lam) * 0.1f;

    const float a = fabsf(x) - lam;
    out[idx] = (a > 0.0f) ? copysignf(a, x) : 0.0f;
}

// ---------------------------------------------------------------------------
// Launch
// ---------------------------------------------------------------------------
extern "C" void kernel_launch(void* const* d_in, const int* in_sizes, int n_in,
                              void* d_out, int out_size)
{
    // 0 theta_12, 1 s_12, 2 w_12, 3 inv_Theta_11, 4 Theta, 5 col,
    // 6 phi_w1, 7 phi_b1, 8 phi_w2, 9 phi_b2, 10 st_w1, 11 st_b1,
    // 12 st_w2, 13 st_b2
    const float* theta12 = (const float*)d_in[0];
    const float* invT    = (const float*)d_in[3];
    const float* phi_w1  = (const float*)d_in[6];
    const float* phi_b1  = (const float*)d_in[7];
    const float* phi_w2  = (const float*)d_in[8];
    const float* phi_b2  = (const float*)d_in[9];
    const float* st_w1   = (const float*)d_in[10];
    const float* st_b1   = (const float*)d_in[11];
    const float* st_w2   = (const float*)d_in[12];
    const float* st_b2   = (const float*)d_in[13];
    float* out = (float*)d_out;

    float* hbuf;   cudaGetSymbolAddress((void**)&hbuf, g_h);
    float* pbuf;   cudaGetSymbolAddress((void**)&pbuf, g_phi_part);

    // GEMM1: h = relu(theta12 @ phi_w1^T + b1)  [256,5120], K=511
    // BM=32, BN=128 -> 128 threads, grid 40x8 = 320 CTAs
    {
        dim3 grid(HDIM / 128, BATCH / 32, 1);
        gemm2x_kernel<32, 128, 16, true, false><<<grid, 128>>>(
            theta12, phi_w1, phi_b1, hbuf, BATCH, HDIM, DDIM, DDIM, HDIM);
    }
    // GEMM2 (split-K): partials = h @ phi_w2^T  [256,511], K=5120
    // BM=64, BN=64 -> 128 threads, grid 8x4x8 = 256 CTAs
    {
        dim3 grid((DDIM + 63) / 64, BATCH / 64, SPLITK);
        gemm2x_kernel<64, 64, 16, false, true><<<grid, 128>>>(
            hbuf, phi_w2, nullptr, pbuf, BATCH, DDIM, HDIM, HDIM / SPLITK, LDC2);
    }
    // reduce partials + bias -> phi
    {
        int n = BATCH * DDIM;
        reduce_phi_kernel<<<(n + 255) / 256, 256>>>(phi_b2);
    }
    // quad partials: phi^T invT phi (lower triangle x2 + diagonal)
    quad_kernel<<<BATCH * QPARTS, 256>>>(invT);

    // epilogue
    {
        int n = BATCH * DDIM;
        epilogue_kernel<<<(n + 255) / 256, 256>>>(st_w1, st_b1, st_w2, st_b2, out);
    }
}